// round 8
// baseline (speedup 1.0000x reference)
#include <cuda_runtime.h>
#include <cuda_bf16.h>
#include <cstddef>

// Problem constants (from reference)
#define BATCH   8192
#define BOX     10
#define PAIR    90                    // BOX*(BOX-1)
#define NUM_QT  65
#define NUM_OT  151
#define PLANE   (NUM_OT * NUM_OT)     // 22801 floats per (qt,pair) plane
#define NPLANES (NUM_QT * PAIR)       // 5850
#define NTHREADS 512
#define GRID     (148 * 4)            // one full wave at 4 CTAs/SM
#define BPT      (BATCH / NTHREADS)   // 16 batches per thread

// ---------------------------------------------------------------------------
// Persistent fused kernel: grid = 592 CTAs, each handles ~10 planes.
//   Prologue (once per CTA): bucket all 8192 batches by qus_type into smem
//     (count -> prefix -> fill).  Amortized over ~10 planes.
//   Per plane: streaming register-blocked float4 copy (proven variant),
//     barrier, then scatter-add the precompacted ~126 entries for this qt.
// ---------------------------------------------------------------------------
__global__ __launch_bounds__(NTHREADS) void fused_persistent_kernel(
        const float* __restrict__ src,
        float*       __restrict__ dst,
        const int*   __restrict__ obj_label,
        const int*   __restrict__ qus_type,
        const float* __restrict__ attention) {
    __shared__ int s_off[NUM_QT + 1];     // bucket offsets
    __shared__ int s_cur[NUM_QT];         // fill cursors
    __shared__ int s_list[BATCH];         // batch ids grouped by qt (32KB)

    int tid = threadIdx.x;

    // ---- Prologue: build qt buckets once ----
    // Phase 1: counts (use s_cur as the count array)
    if (tid < NUM_QT) s_cur[tid] = 0;
    __syncthreads();
    int myqt[BPT];
    #pragma unroll
    for (int k = 0; k < BPT; k++) {
        myqt[k] = __ldg(qus_type + tid * BPT + k);
        atomicAdd(&s_cur[myqt[k]], 1);
    }
    __syncthreads();
    // Phase 2: exclusive prefix (trivial size, one thread)
    if (tid == 0) {
        int run = 0;
        #pragma unroll
        for (int q = 0; q < NUM_QT; q++) {
            s_off[q] = run;
            run += s_cur[q];
        }
        s_off[NUM_QT] = run;              // == BATCH
    }
    __syncthreads();
    if (tid < NUM_QT) s_cur[tid] = s_off[tid];
    __syncthreads();
    // Phase 3: fill
    #pragma unroll
    for (int k = 0; k < BPT; k++) {
        int pos = atomicAdd(&s_cur[myqt[k]], 1);
        s_list[pos] = tid * BPT + k;
    }
    __syncthreads();

    // ---- Plane loop ----
    for (int plane = blockIdx.x; plane < NPLANES; plane += GRID) {
        int qt = plane / PAIR;
        int p  = plane - qt * PAIR;           // pair index 0..89
        size_t base = (size_t)plane * PLANE;

        const float* s = src + base;
        float*       d = dst + base;

        // --- Phase A: copy (proven register-blocked float4 streaming) ---
        int head = (int)((4 - (base & 3)) & 3);     // scalars to 16B alignment
        if (tid < head) __stcs(d + tid, __ldcs(s + tid));

        int nvec = (PLANE - head) >> 2;             // float4 body (~5700)
        const float4* s4 = (const float4*)(s + head);
        float4*       d4 = (float4*)(d + head);

        for (int i0 = tid; i0 < nvec; i0 += 4 * NTHREADS) {
            int i1 = i0 + NTHREADS;
            int i2 = i0 + 2 * NTHREADS;
            int i3 = i0 + 3 * NTHREADS;
            float4 r0, r1, r2, r3;
            bool v1 = i1 < nvec, v2 = i2 < nvec, v3 = i3 < nvec;
            r0 = __ldcs(s4 + i0);
            if (v1) r1 = __ldcs(s4 + i1);
            if (v2) r2 = __ldcs(s4 + i2);
            if (v3) r3 = __ldcs(s4 + i3);
            __stcs(d4 + i0, r0);
            if (v1) __stcs(d4 + i1, r1);
            if (v2) __stcs(d4 + i2, r2);
            if (v3) __stcs(d4 + i3, r3);
        }

        int tail_start = head + (nvec << 2);
        int ntail = PLANE - tail_start;             // 0..3 scalars
        if (tid < ntail) __stcs(d + tail_start + tid, __ldcs(s + tail_start + tid));

        __syncthreads();   // plane fully written before this CTA's atomics

        // --- Phase B: scatter the precompacted entries for this qt ---
        int i  = p / (BOX - 1);
        int jj = p - i * (BOX - 1);
        int j  = jj + (jj >= i);

        int b0 = s_off[qt];
        int b1 = s_off[qt + 1];
        for (int u = b0 + tid; u < b1; u += NTHREADS) {
            int b   = s_list[u];
            int ol1 = __ldg(obj_label + b * BOX + j);
            int ol2 = __ldg(obj_label + b * BOX + i);
            float a = __ldg(attention + b * BOX + i) * __ldg(attention + b * BOX + j);
            atomicAdd(d + ol1 * NUM_OT + ol2, a);
        }
        // No barrier needed here: next iteration's copy touches a disjoint
        // plane, and the next barrier orders everything before its scatter.
    }
}

extern "C" void kernel_launch(void* const* d_in, const int* in_sizes, int n_in,
                              void* d_out, int out_size) {
    const int*   obj_label    = (const int*)d_in[0];
    const int*   qus_type     = (const int*)d_in[1];
    const float* attention    = (const float*)d_in[2];
    const float* score_matrix = (const float*)d_in[3];
    float*       out          = (float*)d_out;

    fused_persistent_kernel<<<GRID, NTHREADS>>>(score_matrix, out,
                                                obj_label, qus_type, attention);
}

// round 9
// speedup vs baseline: 1.1478x; 1.1478x over previous
#include <cuda_runtime.h>
#include <cuda_bf16.h>
#include <cstddef>

// Problem constants (from reference)
#define BATCH   8192
#define BOX     10
#define PAIR    90                    // BOX*(BOX-1)
#define NUM_QT  65
#define NUM_OT  151
#define PLANE   (NUM_OT * NUM_OT)     // 22801 floats per (qt,pair) plane
#define NPLANES (NUM_QT * PAIR)       // 5850
#define NTHREADS 512
#define BK_THREADS 256
#define BK_WARPS   (BK_THREADS / 32)  // 8
#define BK_WIN     (BATCH / BK_WARPS) // 1024 batches per warp window

// Scratch: per-qt compacted batch lists (disjoint segments, no prefix needed)
__device__ int g_list[NUM_QT * BATCH];   // 2 MB
__device__ int g_cnt[NUM_QT];

// ---------------------------------------------------------------------------
// Kernel 1: one CTA per question type. Two-pass warp ballot compaction of
// the 8192 qus_type values (L2-hot) into g_list[qt*BATCH ...]. ~2-3 us.
// ---------------------------------------------------------------------------
__global__ __launch_bounds__(BK_THREADS) void bucket_kernel(
        const int* __restrict__ qus_type) {
    __shared__ int s_wcnt[BK_WARPS];
    __shared__ int s_woff[BK_WARPS];

    int qt   = blockIdx.x;
    int tid  = threadIdx.x;
    int warp = tid >> 5;
    int lane = tid & 31;
    int wbase = warp * BK_WIN;

    // Pass 1: count matches in this warp's window
    int cnt = 0;
    for (int it = 0; it < BK_WIN / 32; it++) {       // 32 iterations
        int b = wbase + it * 32 + lane;
        unsigned m = __ballot_sync(0xFFFFFFFFu, __ldg(qus_type + b) == qt);
        cnt += __popc(m);
    }
    if (lane == 0) s_wcnt[warp] = cnt;
    __syncthreads();

    // Prefix over 8 warp counts
    if (tid == 0) {
        int run = 0;
        #pragma unroll
        for (int w = 0; w < BK_WARPS; w++) {
            s_woff[w] = run;
            run += s_wcnt[w];
        }
        g_cnt[qt] = run;
    }
    __syncthreads();

    // Pass 2: fill (values are L1-hot from pass 1)
    int pos = s_woff[warp];
    int* seg = g_list + qt * BATCH;
    for (int it = 0; it < BK_WIN / 32; it++) {
        int b = wbase + it * 32 + lane;
        bool pred = (__ldg(qus_type + b) == qt);
        unsigned m = __ballot_sync(0xFFFFFFFFu, pred);
        if (pred) seg[pos + __popc(m & ((1u << lane) - 1u))] = b;
        pos += __popc(m);
    }
}

// ---------------------------------------------------------------------------
// Kernel 2: one CTA per (qt, pair) plane — byte-identical copy to the proven
// 162.8us round-4 variant; Phase B reads precompacted entries from g_list.
// ---------------------------------------------------------------------------
__global__ __launch_bounds__(NTHREADS) void fused_plane_kernel(
        const float* __restrict__ src,
        float*       __restrict__ dst,
        const int*   __restrict__ obj_label,
        const float* __restrict__ attention) {
    int plane = blockIdx.x;                 // 0 .. 5849
    int qt = plane / PAIR;
    int p  = plane - qt * PAIR;             // pair index 0..89
    size_t base = (size_t)plane * PLANE;

    const float* s = src + base;
    float*       d = dst + base;
    int tid = threadIdx.x;

    // --- Phase A: copy ---
    int head = (int)((4 - (base & 3)) & 3);         // scalars to reach 16B align
    if (tid < head) __stcs(d + tid, __ldcs(s + tid));

    int nvec = (PLANE - head) >> 2;                 // float4 body count (~5700)
    const float4* s4 = (const float4*)(s + head);
    float4*       d4 = (float4*)(d + head);

    for (int i0 = tid; i0 < nvec; i0 += 4 * NTHREADS) {
        int i1 = i0 + NTHREADS;
        int i2 = i0 + 2 * NTHREADS;
        int i3 = i0 + 3 * NTHREADS;
        float4 r0, r1, r2, r3;
        bool v1 = i1 < nvec, v2 = i2 < nvec, v3 = i3 < nvec;
        r0 = __ldcs(s4 + i0);
        if (v1) r1 = __ldcs(s4 + i1);
        if (v2) r2 = __ldcs(s4 + i2);
        if (v3) r3 = __ldcs(s4 + i3);
        __stcs(d4 + i0, r0);
        if (v1) __stcs(d4 + i1, r1);
        if (v2) __stcs(d4 + i2, r2);
        if (v3) __stcs(d4 + i3, r3);
    }

    int tail_start = head + (nvec << 2);
    int ntail = PLANE - tail_start;                 // 0..3 scalars
    if (tid < ntail) __stcs(d + tail_start + tid, __ldcs(s + tail_start + tid));

    __syncthreads();   // plane fully written before this CTA's atomics

    // --- Phase B: scatter the precompacted entries for this qt ---
    int i  = p / (BOX - 1);
    int jj = p - i * (BOX - 1);
    int j  = jj + (jj >= i);

    int n = g_cnt[qt];
    const int* seg = g_list + qt * BATCH;
    for (int u = tid; u < n; u += NTHREADS) {
        int b   = __ldg(seg + u);
        int ol1 = __ldg(obj_label + b * BOX + j);
        int ol2 = __ldg(obj_label + b * BOX + i);
        float a = __ldg(attention + b * BOX + i) * __ldg(attention + b * BOX + j);
        atomicAdd(d + ol1 * NUM_OT + ol2, a);
    }
}

extern "C" void kernel_launch(void* const* d_in, const int* in_sizes, int n_in,
                              void* d_out, int out_size) {
    const int*   obj_label    = (const int*)d_in[0];
    const int*   qus_type     = (const int*)d_in[1];
    const float* attention    = (const float*)d_in[2];
    const float* score_matrix = (const float*)d_in[3];
    float*       out          = (float*)d_out;

    bucket_kernel<<<NUM_QT, BK_THREADS>>>(qus_type);
    fused_plane_kernel<<<NPLANES, NTHREADS>>>(score_matrix, out,
                                              obj_label, attention);
}

// round 10
// speedup vs baseline: 1.1553x; 1.0065x over previous
#include <cuda_runtime.h>
#include <cuda_bf16.h>
#include <cstddef>

// Problem constants (from reference)
#define BATCH   8192
#define BOX     10
#define PAIR    90                    // BOX*(BOX-1)
#define NUM_QT  65
#define NUM_OT  151
#define PLANE   (NUM_OT * NUM_OT)     // 22801 floats per (qt,pair) plane
#define NPLANES (NUM_QT * PAIR)       // 5850
#define NTHREADS 512
#define BK_THREADS 1024
#define BK_WARPS   (BK_THREADS / 32)      // 32
#define BK_PER_LANE (BATCH / BK_THREADS)  // 8 values per lane

// Scratch: per-qt compacted batch lists (disjoint segments, no prefix needed)
__device__ int g_list[NUM_QT * BATCH];   // 2 MB
__device__ int g_cnt[NUM_QT];

// ---------------------------------------------------------------------------
// Kernel 1: one CTA per question type. Latency-tolerant compaction:
//   prefetch all 8 values/lane into registers (ONE memory round trip),
//   then ballot/popc entirely on register data. ~1.5-2us total.
// ---------------------------------------------------------------------------
__global__ __launch_bounds__(BK_THREADS) void bucket_kernel(
        const int* __restrict__ qus_type) {
    __shared__ int s_wcnt[BK_WARPS];
    __shared__ int s_woff[BK_WARPS];

    int qt   = blockIdx.x;
    int tid  = threadIdx.x;
    int warp = tid >> 5;
    int lane = tid & 31;
    int wbase = warp * (BK_PER_LANE * 32);   // 256 batches per warp

    // Batched prefetch: 8 independent LDGs, all in flight together.
    int vals[BK_PER_LANE];
    #pragma unroll
    for (int k = 0; k < BK_PER_LANE; k++)
        vals[k] = __ldg(qus_type + wbase + k * 32 + lane);

    // Ballot rounds on register data; save masks for the fill pass.
    unsigned masks[BK_PER_LANE];
    int cnt = 0;
    #pragma unroll
    for (int k = 0; k < BK_PER_LANE; k++) {
        masks[k] = __ballot_sync(0xFFFFFFFFu, vals[k] == qt);
        cnt += __popc(masks[k]);
    }
    if (lane == 0) s_wcnt[warp] = cnt;
    __syncthreads();

    // Prefix over 32 warp counts (single thread; 32 smem reads, trivial)
    if (tid == 0) {
        int run = 0;
        #pragma unroll
        for (int w = 0; w < BK_WARPS; w++) {
            s_woff[w] = run;
            run += s_wcnt[w];
        }
        g_cnt[qt] = run;
    }
    __syncthreads();

    // Fill from registers (no reload)
    int pos = s_woff[warp];
    int* seg = g_list + qt * BATCH;
    unsigned lt = (1u << lane) - 1u;
    #pragma unroll
    for (int k = 0; k < BK_PER_LANE; k++) {
        if (vals[k] == qt)
            seg[pos + __popc(masks[k] & lt)] = wbase + k * 32 + lane;
        pos += __popc(masks[k]);
    }
}

// ---------------------------------------------------------------------------
// Kernel 2: one CTA per (qt, pair) plane — byte-identical copy to the proven
// 162.8us round-4 variant; Phase B reads precompacted entries from g_list.
// ---------------------------------------------------------------------------
__global__ __launch_bounds__(NTHREADS) void fused_plane_kernel(
        const float* __restrict__ src,
        float*       __restrict__ dst,
        const int*   __restrict__ obj_label,
        const float* __restrict__ attention) {
    int plane = blockIdx.x;                 // 0 .. 5849
    int qt = plane / PAIR;
    int p  = plane - qt * PAIR;             // pair index 0..89
    size_t base = (size_t)plane * PLANE;

    const float* s = src + base;
    float*       d = dst + base;
    int tid = threadIdx.x;

    // --- Phase A: copy ---
    int head = (int)((4 - (base & 3)) & 3);         // scalars to reach 16B align
    if (tid < head) __stcs(d + tid, __ldcs(s + tid));

    int nvec = (PLANE - head) >> 2;                 // float4 body count (~5700)
    const float4* s4 = (const float4*)(s + head);
    float4*       d4 = (float4*)(d + head);

    for (int i0 = tid; i0 < nvec; i0 += 4 * NTHREADS) {
        int i1 = i0 + NTHREADS;
        int i2 = i0 + 2 * NTHREADS;
        int i3 = i0 + 3 * NTHREADS;
        float4 r0, r1, r2, r3;
        bool v1 = i1 < nvec, v2 = i2 < nvec, v3 = i3 < nvec;
        r0 = __ldcs(s4 + i0);
        if (v1) r1 = __ldcs(s4 + i1);
        if (v2) r2 = __ldcs(s4 + i2);
        if (v3) r3 = __ldcs(s4 + i3);
        __stcs(d4 + i0, r0);
        if (v1) __stcs(d4 + i1, r1);
        if (v2) __stcs(d4 + i2, r2);
        if (v3) __stcs(d4 + i3, r3);
    }

    int tail_start = head + (nvec << 2);
    int ntail = PLANE - tail_start;                 // 0..3 scalars
    if (tid < ntail) __stcs(d + tail_start + tid, __ldcs(s + tail_start + tid));

    __syncthreads();   // plane fully written before this CTA's atomics

    // --- Phase B: scatter the precompacted entries for this qt ---
    int i  = p / (BOX - 1);
    int jj = p - i * (BOX - 1);
    int j  = jj + (jj >= i);

    int n = g_cnt[qt];
    const int* seg = g_list + qt * BATCH;
    for (int u = tid; u < n; u += NTHREADS) {
        int b   = __ldg(seg + u);
        int ol1 = __ldg(obj_label + b * BOX + j);
        int ol2 = __ldg(obj_label + b * BOX + i);
        float a = __ldg(attention + b * BOX + i) * __ldg(attention + b * BOX + j);
        atomicAdd(d + ol1 * NUM_OT + ol2, a);
    }
}

extern "C" void kernel_launch(void* const* d_in, const int* in_sizes, int n_in,
                              void* d_out, int out_size) {
    const int*   obj_label    = (const int*)d_in[0];
    const int*   qus_type     = (const int*)d_in[1];
    const float* attention    = (const float*)d_in[2];
    const float* score_matrix = (const float*)d_in[3];
    float*       out          = (float*)d_out;

    bucket_kernel<<<NUM_QT, BK_THREADS>>>(qus_type);
    fused_plane_kernel<<<NPLANES, NTHREADS>>>(score_matrix, out,
                                              obj_label, attention);
}

// round 12
// speedup vs baseline: 1.1661x; 1.0093x over previous
#include <cuda_runtime.h>
#include <cuda_bf16.h>
#include <cstddef>

// Problem constants (from reference)
#define BATCH   8192
#define BOX     10
#define PAIR    90                    // BOX*(BOX-1)
#define NUM_QT  65
#define NUM_OT  151
#define PLANE   (NUM_OT * NUM_OT)     // 22801 floats per (qt,pair) plane
#define NPLANES (NUM_QT * PAIR)       // 5850
#define NTHREADS 512
#define BK_THREADS 1024
#define BK_WARPS   (BK_THREADS / 32)      // 32
#define BK_PER_LANE (BATCH / BK_THREADS)  // 8 values per lane

// Scratch: per-qt compacted batch lists (disjoint segments, no prefix needed)
__device__ int g_list[NUM_QT * BATCH];   // 2 MB
__device__ int g_cnt[NUM_QT];

// ---------------------------------------------------------------------------
// Kernel 1 (PDL primary): one CTA per question type. Fires launch_dependents
// at entry so the copy kernel starts concurrently; compaction is latency-
// batched (one memory round trip) and finishes ~145us before anyone reads it.
// ---------------------------------------------------------------------------
__global__ __launch_bounds__(BK_THREADS) void bucket_kernel(
        const int* __restrict__ qus_type) {
    // Let the dependent (copy) grid launch immediately.
    asm volatile("griddepcontrol.launch_dependents;");

    __shared__ int s_wcnt[BK_WARPS];
    __shared__ int s_woff[BK_WARPS];

    int qt   = blockIdx.x;
    int tid  = threadIdx.x;
    int warp = tid >> 5;
    int lane = tid & 31;
    int wbase = warp * (BK_PER_LANE * 32);   // 256 batches per warp

    // Batched prefetch: 8 independent LDGs, all in flight together.
    int vals[BK_PER_LANE];
    #pragma unroll
    for (int k = 0; k < BK_PER_LANE; k++)
        vals[k] = __ldg(qus_type + wbase + k * 32 + lane);

    unsigned masks[BK_PER_LANE];
    int cnt = 0;
    #pragma unroll
    for (int k = 0; k < BK_PER_LANE; k++) {
        masks[k] = __ballot_sync(0xFFFFFFFFu, vals[k] == qt);
        cnt += __popc(masks[k]);
    }
    if (lane == 0) s_wcnt[warp] = cnt;
    __syncthreads();

    if (tid == 0) {
        int run = 0;
        #pragma unroll
        for (int w = 0; w < BK_WARPS; w++) {
            s_woff[w] = run;
            run += s_wcnt[w];
        }
        g_cnt[qt] = run;
    }
    __syncthreads();

    int pos = s_woff[warp];
    int* seg = g_list + qt * BATCH;
    unsigned lt = (1u << lane) - 1u;
    #pragma unroll
    for (int k = 0; k < BK_PER_LANE; k++) {
        if (vals[k] == qt)
            seg[pos + __popc(masks[k] & lt)] = wbase + k * 32 + lane;
        pos += __popc(masks[k]);
    }
}

// ---------------------------------------------------------------------------
// Kernel 2 (PDL secondary): one CTA per (qt, pair) plane. Phase A copy runs
// CONCURRENTLY with the bucket kernel; griddepcontrol.wait before Phase B
// guarantees g_list/g_cnt visibility.
// ---------------------------------------------------------------------------
__global__ __launch_bounds__(NTHREADS) void fused_plane_kernel(
        const float* __restrict__ src,
        float*       __restrict__ dst,
        const int*   __restrict__ obj_label,
        const float* __restrict__ attention) {
    int plane = blockIdx.x;                 // 0 .. 5849
    int qt = plane / PAIR;
    int p  = plane - qt * PAIR;             // pair index 0..89
    size_t base = (size_t)plane * PLANE;

    const float* s = src + base;
    float*       d = dst + base;
    int tid = threadIdx.x;

    // --- Phase A: copy (proven register-blocked float4 streaming) ---
    int head = (int)((4 - (base & 3)) & 3);         // scalars to reach 16B align
    if (tid < head) __stcs(d + tid, __ldcs(s + tid));

    int nvec = (PLANE - head) >> 2;                 // float4 body count (~5700)
    const float4* s4 = (const float4*)(s + head);
    float4*       d4 = (float4*)(d + head);

    for (int i0 = tid; i0 < nvec; i0 += 4 * NTHREADS) {
        int i1 = i0 + NTHREADS;
        int i2 = i0 + 2 * NTHREADS;
        int i3 = i0 + 3 * NTHREADS;
        float4 r0, r1, r2, r3;
        bool v1 = i1 < nvec, v2 = i2 < nvec, v3 = i3 < nvec;
        r0 = __ldcs(s4 + i0);
        if (v1) r1 = __ldcs(s4 + i1);
        if (v2) r2 = __ldcs(s4 + i2);
        if (v3) r3 = __ldcs(s4 + i3);
        __stcs(d4 + i0, r0);
        if (v1) __stcs(d4 + i1, r1);
        if (v2) __stcs(d4 + i2, r2);
        if (v3) __stcs(d4 + i3, r3);
    }

    int tail_start = head + (nvec << 2);
    int ntail = PLANE - tail_start;                 // 0..3 scalars
    if (tid < ntail) __stcs(d + tail_start + tid, __ldcs(s + tail_start + tid));

    // Wait for the bucket kernel's writes to be visible (retires instantly in
    // practice — the bucket finished during the ~150us copy above).
    asm volatile("griddepcontrol.wait;" ::: "memory");

    __syncthreads();   // plane fully written before this CTA's atomics

    // --- Phase B: scatter the precompacted entries for this qt ---
    int i  = p / (BOX - 1);
    int jj = p - i * (BOX - 1);
    int j  = jj + (jj >= i);

    int n = g_cnt[qt];
    const int* seg = g_list + qt * BATCH;
    for (int u = tid; u < n; u += NTHREADS) {
        int b   = __ldg(seg + u);
        int ol1 = __ldg(obj_label + b * BOX + j);
        int ol2 = __ldg(obj_label + b * BOX + i);
        float a = __ldg(attention + b * BOX + i) * __ldg(attention + b * BOX + j);
        atomicAdd(d + ol1 * NUM_OT + ol2, a);
    }
}

extern "C" void kernel_launch(void* const* d_in, const int* in_sizes, int n_in,
                              void* d_out, int out_size) {
    const int*   obj_label    = (const int*)d_in[0];
    const int*   qus_type     = (const int*)d_in[1];
    const float* attention    = (const float*)d_in[2];
    const float* score_matrix = (const float*)d_in[3];
    float*       out          = (float*)d_out;

    // Primary: bucket build (fires launch_dependents at entry)
    bucket_kernel<<<NUM_QT, BK_THREADS>>>(qus_type);

    // Secondary: launched with Programmatic Stream Serialization so its
    // copy phase overlaps the bucket kernel.
    cudaLaunchConfig_t cfg = {};
    cfg.gridDim  = dim3(NPLANES);
    cfg.blockDim = dim3(NTHREADS);
    cfg.dynamicSmemBytes = 0;
    cfg.stream = 0;
    cudaLaunchAttribute attr[1];
    attr[0].id = cudaLaunchAttributeProgrammaticStreamSerialization;
    attr[0].val.programmaticStreamSerializationAllowed = 1;
    cfg.attrs = attr;
    cfg.numAttrs = 1;
    cudaLaunchKernelEx(&cfg, fused_plane_kernel,
                       score_matrix, out, obj_label, attention);
}